// round 3
// baseline (speedup 1.0000x reference)
#include <cuda_runtime.h>
#include <cstdint>

#define NN 50000
#define NE 800000

// ---------------- packed f32x2 helpers ----------------
#define FMA2(acc, a, b) \
    asm("fma.rn.f32x2 %0, %1, %2, %0;" : "+l"(acc) : "l"(a), "l"(b))
#define PACK_DUP(out, f) \
    asm("mov.b64 %0, {%1, %1};" : "=l"(out) : "f"(f))
#define UNPACK2(lo, hi, in) \
    asm("mov.b64 {%0, %1}, %2;" : "=f"(lo), "=f"(hi) : "l"(in))

// ---------------- scratch (device globals; no allocation allowed) ----------------
__device__ __align__(16) float g_agg[NN * 96];
__device__ __align__(16) float g_h1 [NN * 96];
__device__ __align__(16) float g_h2 [NN * 64];
__device__ __align__(16) float g_h3 [NN * 96];
__device__ __align__(16) float g_h4 [NN * 96];
__device__ __align__(16) float g_h5 [NN * 16];
__device__ __align__(16) float g_sum[96];
__device__ __align__(16) float g_sq [96];
__device__ __align__(16) float g_sc [5][96];
__device__ __align__(16) float g_sh [5][96];
// CSR scratch
__device__ int   g_deg      [NN];
__device__ int   g_row_start[NN];
__device__ int   g_pos      [NN];
__device__ int   g_csr_src  [NE];
__device__ float g_csr_ea   [NE];

// ---------------- CSR build ----------------
__global__ void hist_kernel(const int* __restrict__ dst, int* __restrict__ deg)
{
    int i = blockIdx.x * blockDim.x + threadIdx.x;
    if (i < NE) atomicAdd(&deg[dst[i]], 1);
}

__global__ void scan_kernel(const int* __restrict__ deg,
                            int* __restrict__ row_start,
                            int* __restrict__ pos)
{
    constexpr int T = 1024;
    constexpr int CH = (NN + T - 1) / T;
    __shared__ int warp_sums[32];
    int t = threadIdx.x;
    int base = t * CH;

    int s = 0;
    for (int i = 0; i < CH; i++) {
        int idx = base + i;
        if (idx < NN) s += deg[idx];
    }
    int lane = t & 31, wid = t >> 5;
    int v = s;
#pragma unroll
    for (int o = 1; o < 32; o <<= 1) {
        int u = __shfl_up_sync(0xffffffff, v, o);
        if (lane >= o) v += u;
    }
    if (lane == 31) warp_sums[wid] = v;
    __syncthreads();
    if (wid == 0) {
        int w = warp_sums[lane];
#pragma unroll
        for (int o = 1; o < 32; o <<= 1) {
            int u = __shfl_up_sync(0xffffffff, w, o);
            if (lane >= o) w += u;
        }
        warp_sums[lane] = w;
    }
    __syncthreads();
    int excl = v - s + (wid > 0 ? warp_sums[wid - 1] : 0);

    int running = excl;
    for (int i = 0; i < CH; i++) {
        int idx = base + i;
        if (idx < NN) {
            row_start[idx] = running;
            pos[idx]       = running;
            running += deg[idx];
        }
    }
}

__global__ void scatter_kernel(const int* __restrict__ src,
                               const int* __restrict__ dst,
                               const float* __restrict__ ea,
                               int* __restrict__ pos,
                               int* __restrict__ csr_src,
                               float* __restrict__ csr_ea)
{
    int i = blockIdx.x * blockDim.x + threadIdx.x;
    if (i >= NE) return;
    int slot = atomicAdd(&pos[dst[i]], 1);
    csr_src[slot] = src[i];
    csr_ea [slot] = ea[i];
}

// ---------------- warp-per-node CSR aggregation ----------------
// agg[n][:] = sum_e relu(affine(x[src_e]) + (a_e*lw + lb))
// 8 warps/block, 1 node/warp. Within a warp: 4 edges processed concurrently by
// 8-lane groups; each lane owns 3 float4 column-chunks (cols (sub+8j)*4).
__global__ void aggregate_kernel(const float* __restrict__ xin,
                                 const float* __restrict__ sc,
                                 const float* __restrict__ sh,
                                 const float* __restrict__ lw,
                                 const float* __restrict__ lb,
                                 const int* __restrict__ row_start,
                                 const int* __restrict__ deg,
                                 const int* __restrict__ csr_src,
                                 const float* __restrict__ csr_ea,
                                 float* __restrict__ agg)
{
    int w    = threadIdx.x >> 5;
    int lane = threadIdx.x & 31;
    int node = blockIdx.x * 8 + w;
    if (node >= NN) return;

    int g   = lane >> 3;   // edge slot within 4-edge batch
    int sub = lane & 7;    // chunk lane

    const bool aff = (sc != nullptr);
    float4 lw4[3], lb4[3], sc4[3], sh4[3];
#pragma unroll
    for (int j = 0; j < 3; j++) {
        int c = sub + 8 * j;
        lw4[j] = reinterpret_cast<const float4*>(lw)[c];
        lb4[j] = reinterpret_cast<const float4*>(lb)[c];
        if (aff) {
            sc4[j] = reinterpret_cast<const float4*>(sc)[c];
            sh4[j] = reinterpret_cast<const float4*>(sh)[c];
        }
    }

    int s0 = row_start[node];
    int d  = deg[node];

    float4 acc[3];
#pragma unroll
    for (int j = 0; j < 3; j++) acc[j] = make_float4(0.f, 0.f, 0.f, 0.f);

    for (int e0 = 0; e0 < d; e0 += 4) {
        int e = e0 + g;
        if (e < d) {
            int   s = csr_src[s0 + e];   // broadcast within group
            float a = csr_ea [s0 + e];
            const float4* xr = reinterpret_cast<const float4*>(xin + (size_t)s * 96);
#pragma unroll
            for (int j = 0; j < 3; j++) {
                float4 xv = xr[sub + 8 * j];
                if (aff) {
                    xv.x = fmaf(xv.x, sc4[j].x, sh4[j].x);
                    xv.y = fmaf(xv.y, sc4[j].y, sh4[j].y);
                    xv.z = fmaf(xv.z, sc4[j].z, sh4[j].z);
                    xv.w = fmaf(xv.w, sc4[j].w, sh4[j].w);
                }
                acc[j].x += fmaxf(fmaf(a, lw4[j].x, lb4[j].x) + xv.x, 0.f);
                acc[j].y += fmaxf(fmaf(a, lw4[j].y, lb4[j].y) + xv.y, 0.f);
                acc[j].z += fmaxf(fmaf(a, lw4[j].z, lb4[j].z) + xv.z, 0.f);
                acc[j].w += fmaxf(fmaf(a, lw4[j].w, lb4[j].w) + xv.w, 0.f);
            }
        }
    }

    // cross-group reduction (4 groups -> group 0)
#pragma unroll
    for (int off = 8; off <= 16; off <<= 1) {
#pragma unroll
        for (int j = 0; j < 3; j++) {
            acc[j].x += __shfl_xor_sync(0xffffffff, acc[j].x, off);
            acc[j].y += __shfl_xor_sync(0xffffffff, acc[j].y, off);
            acc[j].z += __shfl_xor_sync(0xffffffff, acc[j].z, off);
            acc[j].w += __shfl_xor_sync(0xffffffff, acc[j].w, off);
        }
    }
    if (g == 0) {
        float4* ar = reinterpret_cast<float4*>(agg + (size_t)node * 96);
#pragma unroll
        for (int j = 0; j < 3; j++) ar[sub + 8 * j] = acc[j];
    }
}

// ---------------- FFMA2 GEMM + bias + ReLU + BN stats ----------------
// Per-thread micro-tile: 8 rows x 8 cols using fma.rn.f32x2 (row pairs packed).
// input row = affine(A)(+Aadd) for cols < K1, affine2(B2) for cols >= K1.
template<int BN, int TX, int TY>
__global__ void gemm_kernel(const float* __restrict__ A,
                            const float* __restrict__ scA,
                            const float* __restrict__ shA,
                            const float* __restrict__ Aadd,
                            const float* __restrict__ B2,
                            const float* __restrict__ scB,
                            const float* __restrict__ shB,
                            int K, int K1,
                            const float* __restrict__ W,
                            const float* __restrict__ bias,
                            float* __restrict__ H,
                            float* __restrict__ gsum,
                            float* __restrict__ gsumsq,
                            int M)
{
    constexpr int BK = 32;
    constexpr int BM = TY * 8;
    constexpr int THREADS = TX * TY;
    constexpr int S = BM + 8;            // keeps &At[k][8*ty] 16B-aligned

    __shared__ float At[BK][S];
    __shared__ float Wt[BK][BN];
    __shared__ float s_sum[BN];
    __shared__ float s_sq [BN];

    const int tid = threadIdx.x;
    const int tx  = tid % TX;
    const int ty  = tid / TX;
    const int m0  = blockIdx.x * BM;
    const int K2  = K - K1;

    for (int t = tid; t < BN; t += THREADS) { s_sum[t] = 0.f; s_sq[t] = 0.f; }

    unsigned long long acc[4][8];
#pragma unroll
    for (int rp = 0; rp < 4; rp++)
#pragma unroll
        for (int c = 0; c < 8; c++) acc[rp][c] = 0ull;

    for (int kb = 0; kb < K; kb += BK) {
        // A tile (transposed)
        for (int t = tid; t < BM * 8; t += THREADS) {
            int m  = t >> 3;
            int k4 = (t & 7) * 4;
            int row = m0 + m;
            float4 v = make_float4(0.f, 0.f, 0.f, 0.f);
            if (row < M) {
                int gc = kb + k4;
                if (B2 != nullptr && gc >= K1) {
                    int c2 = gc - K1;
                    v = *reinterpret_cast<const float4*>(B2 + (size_t)row * K2 + c2);
                    if (scB != nullptr) {
                        float4 sc4 = *reinterpret_cast<const float4*>(scB + c2);
                        float4 sh4 = *reinterpret_cast<const float4*>(shB + c2);
                        v.x = fmaf(v.x, sc4.x, sh4.x);
                        v.y = fmaf(v.y, sc4.y, sh4.y);
                        v.z = fmaf(v.z, sc4.z, sh4.z);
                        v.w = fmaf(v.w, sc4.w, sh4.w);
                    }
                } else {
                    v = *reinterpret_cast<const float4*>(A + (size_t)row * K1 + gc);
                    if (scA != nullptr) {
                        float4 sc4 = *reinterpret_cast<const float4*>(scA + gc);
                        float4 sh4 = *reinterpret_cast<const float4*>(shA + gc);
                        v.x = fmaf(v.x, sc4.x, sh4.x);
                        v.y = fmaf(v.y, sc4.y, sh4.y);
                        v.z = fmaf(v.z, sc4.z, sh4.z);
                        v.w = fmaf(v.w, sc4.w, sh4.w);
                    }
                    if (Aadd != nullptr) {
                        float4 v2 = *reinterpret_cast<const float4*>(Aadd + (size_t)row * K1 + gc);
                        v.x += v2.x; v.y += v2.y; v.z += v2.z; v.w += v2.w;
                    }
                }
            }
            At[k4 + 0][m] = v.x;
            At[k4 + 1][m] = v.y;
            At[k4 + 2][m] = v.z;
            At[k4 + 3][m] = v.w;
        }
        // W tile
        for (int t = tid; t < BK * (BN / 4); t += THREADS) {
            int k  = t / (BN / 4);
            int c4 = (t % (BN / 4)) * 4;
            float4 v = *reinterpret_cast<const float4*>(W + (size_t)(kb + k) * BN + c4);
            *reinterpret_cast<float4*>(&Wt[k][c4]) = v;
        }
        __syncthreads();

#pragma unroll 4
        for (int k = 0; k < BK; k++) {
            ulonglong2 a01 = *reinterpret_cast<const ulonglong2*>(&At[k][ty * 8]);
            ulonglong2 a23 = *reinterpret_cast<const ulonglong2*>(&At[k][ty * 8 + 4]);
            float4 w0 = *reinterpret_cast<const float4*>(&Wt[k][tx * 8]);
            float4 w1 = *reinterpret_cast<const float4*>(&Wt[k][tx * 8 + 4]);
            unsigned long long wd[8];
            PACK_DUP(wd[0], w0.x); PACK_DUP(wd[1], w0.y);
            PACK_DUP(wd[2], w0.z); PACK_DUP(wd[3], w0.w);
            PACK_DUP(wd[4], w1.x); PACK_DUP(wd[5], w1.y);
            PACK_DUP(wd[6], w1.z); PACK_DUP(wd[7], w1.w);
            unsigned long long ap[4] = {a01.x, a01.y, a23.x, a23.y};
#pragma unroll
            for (int rp = 0; rp < 4; rp++)
#pragma unroll
                for (int c = 0; c < 8; c++)
                    FMA2(acc[rp][c], ap[rp], wd[c]);
        }
        __syncthreads();
    }

    // epilogue: bias + relu + store + BN stats
    const int c0 = tx * 8;
    float bs[8];
#pragma unroll
    for (int c = 0; c < 8; c++) bs[c] = bias[c0 + c];
    float csum[8], csq[8];
#pragma unroll
    for (int c = 0; c < 8; c++) { csum[c] = 0.f; csq[c] = 0.f; }

#pragma unroll
    for (int rp = 0; rp < 4; rp++) {
        float r0v[8], r1v[8];
#pragma unroll
        for (int c = 0; c < 8; c++) UNPACK2(r0v[c], r1v[c], acc[rp][c]);
        int row0 = m0 + ty * 8 + 2 * rp;
#pragma unroll
        for (int rr = 0; rr < 2; rr++) {
            int row = row0 + rr;
            if (row < M) {
                float* rv = rr ? r1v : r0v;
                float o[8];
#pragma unroll
                for (int c = 0; c < 8; c++) {
                    o[c] = fmaxf(rv[c] + bs[c], 0.f);
                    csum[c] += o[c];
                    csq [c] += o[c] * o[c];
                }
                float4* hp = reinterpret_cast<float4*>(H + (size_t)row * BN + c0);
                hp[0] = make_float4(o[0], o[1], o[2], o[3]);
                hp[1] = make_float4(o[4], o[5], o[6], o[7]);
            }
        }
    }
#pragma unroll
    for (int c = 0; c < 8; c++) {
        atomicAdd(&s_sum[c0 + c], csum[c]);
        atomicAdd(&s_sq [c0 + c], csq[c]);
    }
    __syncthreads();
    for (int t = tid; t < BN; t += THREADS) {
        atomicAdd(gsum   + t, s_sum[t]);
        atomicAdd(gsumsq + t, s_sq[t]);
    }
}

// ---------------- BN finalize ----------------
__global__ void finalize_kernel(const float* __restrict__ gsum,
                                const float* __restrict__ gsumsq,
                                const float* __restrict__ g,
                                const float* __restrict__ beta,
                                float* __restrict__ scale,
                                float* __restrict__ shift,
                                int BNc, int M)
{
    int t = threadIdx.x;
    if (t < BNc) {
        float invM = 1.0f / (float)M;
        float mu   = gsum[t] * invM;
        float var  = gsumsq[t] * invM - mu * mu;
        float inv  = rsqrtf(var + 1e-5f);
        float sc   = g[t] * inv;
        scale[t] = sc;
        shift[t] = fmaf(-mu, sc, beta[t]);
    }
}

// ---------------- final output normalize ----------------
__global__ void norm_kernel(const float* __restrict__ Hin,
                            const float* __restrict__ scale,
                            const float* __restrict__ shift,
                            float* __restrict__ out,
                            int n4, int cols4)
{
    int i = blockIdx.x * blockDim.x + threadIdx.x;
    if (i >= n4) return;
    int c4 = (i % cols4) * 4;
    float4 v  = reinterpret_cast<const float4*>(Hin)[i];
    float4 sc = *reinterpret_cast<const float4*>(scale + c4);
    float4 sh = *reinterpret_cast<const float4*>(shift + c4);
    float4 r;
    r.x = fmaf(v.x, sc.x, sh.x);
    r.y = fmaf(v.y, sc.y, sh.y);
    r.z = fmaf(v.z, sc.z, sh.z);
    r.w = fmaf(v.w, sc.w, sh.w);
    reinterpret_cast<float4*>(out)[i] = r;
}

// ---------------- host orchestration ----------------
extern "C" void kernel_launch(void* const* d_in, const int* in_sizes, int n_in,
                              void* d_out, int out_size)
{
    const float* x   = (const float*)d_in[0];
    const float* ea  = (const float*)d_in[1];
    const int*   ei  = (const int*)  d_in[2];
    const float* lw  = (const float*)d_in[3];
    const float* lb  = (const float*)d_in[4];
    const float* w1  = (const float*)d_in[5];
    const float* b1  = (const float*)d_in[6];
    const float* g1  = (const float*)d_in[7];
    const float* be1 = (const float*)d_in[8];
    const float* w2  = (const float*)d_in[9];
    const float* b2  = (const float*)d_in[10];
    const float* g2  = (const float*)d_in[11];
    const float* be2 = (const float*)d_in[12];
    const float* w3  = (const float*)d_in[13];
    const float* b3  = (const float*)d_in[14];
    const float* g3  = (const float*)d_in[15];
    const float* be3 = (const float*)d_in[16];
    const float* w4  = (const float*)d_in[17];
    const float* b4  = (const float*)d_in[18];
    const float* g4  = (const float*)d_in[19];
    const float* be4 = (const float*)d_in[20];
    const float* w5  = (const float*)d_in[21];
    const float* b5  = (const float*)d_in[22];
    const float* g5  = (const float*)d_in[23];
    const float* be5 = (const float*)d_in[24];
    float* out = (float*)d_out;

    const int* srcp = ei;
    const int* dstp = ei + NE;

    float *agg, *h1, *h2, *h3, *h4, *h5, *sum, *sq, *scb, *shb;
    int *deg, *row_start, *pos, *csr_src;
    float *csr_ea;
    cudaGetSymbolAddress((void**)&agg,       g_agg);
    cudaGetSymbolAddress((void**)&h1,        g_h1);
    cudaGetSymbolAddress((void**)&h2,        g_h2);
    cudaGetSymbolAddress((void**)&h3,        g_h3);
    cudaGetSymbolAddress((void**)&h4,        g_h4);
    cudaGetSymbolAddress((void**)&h5,        g_h5);
    cudaGetSymbolAddress((void**)&sum,       g_sum);
    cudaGetSymbolAddress((void**)&sq,        g_sq);
    cudaGetSymbolAddress((void**)&scb,       g_sc);
    cudaGetSymbolAddress((void**)&shb,       g_sh);
    cudaGetSymbolAddress((void**)&deg,       g_deg);
    cudaGetSymbolAddress((void**)&row_start, g_row_start);
    cudaGetSymbolAddress((void**)&pos,       g_pos);
    cudaGetSymbolAddress((void**)&csr_src,   g_csr_src);
    cudaGetSymbolAddress((void**)&csr_ea,    g_csr_ea);

    float* sc1 = scb + 0 * 96; float* sh1 = shb + 0 * 96;
    float* sc2 = scb + 1 * 96; float* sh2 = shb + 1 * 96;
    float* sc3 = scb + 2 * 96; float* sh3 = shb + 2 * 96;
    float* sc4 = scb + 3 * 96; float* sh4 = shb + 3 * 96;
    float* sc5 = scb + 4 * 96; float* sh5 = shb + 4 * 96;

    const int M = NN;
    const int eblk = (NE + 255) / 256;
    const int ablocks = (NN + 7) / 8;

    // ---- CSR build (shared by both convs) ----
    cudaMemsetAsync(deg, 0, NN * sizeof(int), 0);
    hist_kernel<<<eblk, 256>>>(dstp, deg);
    scan_kernel<<<1, 1024>>>(deg, row_start, pos);
    scatter_kernel<<<eblk, 256>>>(srcp, dstp, ea, pos, csr_src, csr_ea);

    // ---- conv1 ----
    aggregate_kernel<<<ablocks, 256>>>(x, nullptr, nullptr, lw, lb,
                                       row_start, deg, csr_src, csr_ea, agg);
    cudaMemsetAsync(sum, 0, 96 * sizeof(float), 0);
    cudaMemsetAsync(sq,  0, 96 * sizeof(float), 0);
    gemm_kernel<96, 12, 8><<<(M + 63) / 64, 96>>>(x, nullptr, nullptr, agg,
                                                  nullptr, nullptr, nullptr,
                                                  96, 96, w1, b1, h1, sum, sq, M);
    finalize_kernel<<<1, 96>>>(sum, sq, g1, be1, sc1, sh1, 96, M);

    // ---- conv2 ----
    aggregate_kernel<<<ablocks, 256>>>(h1, sc1, sh1, lw, lb,
                                       row_start, deg, csr_src, csr_ea, agg);
    cudaMemsetAsync(sum, 0, 96 * sizeof(float), 0);
    cudaMemsetAsync(sq,  0, 96 * sizeof(float), 0);
    gemm_kernel<64, 8, 16><<<(M + 127) / 128, 128>>>(h1, sc1, sh1, agg,
                                                     nullptr, nullptr, nullptr,
                                                     96, 96, w2, b2, h2, sum, sq, M);
    finalize_kernel<<<1, 64>>>(sum, sq, g2, be2, sc2, sh2, 64, M);

    // ---- lin1: concat(affine(h1), affine(h2)) @ w3 ----
    cudaMemsetAsync(sum, 0, 96 * sizeof(float), 0);
    cudaMemsetAsync(sq,  0, 96 * sizeof(float), 0);
    gemm_kernel<96, 12, 8><<<(M + 63) / 64, 96>>>(h1, sc1, sh1, nullptr,
                                                  h2, sc2, sh2,
                                                  160, 96, w3, b3, h3, sum, sq, M);
    finalize_kernel<<<1, 96>>>(sum, sq, g3, be3, sc3, sh3, 96, M);

    // ---- mlp1a ----
    cudaMemsetAsync(sum, 0, 96 * sizeof(float), 0);
    cudaMemsetAsync(sq,  0, 96 * sizeof(float), 0);
    gemm_kernel<96, 12, 8><<<(M + 63) / 64, 96>>>(h3, sc3, sh3, nullptr,
                                                  nullptr, nullptr, nullptr,
                                                  96, 96, w4, b4, h4, sum, sq, M);
    finalize_kernel<<<1, 96>>>(sum, sq, g4, be4, sc4, sh4, 96, M);

    // ---- mlp1b -> output ----
    cudaMemsetAsync(sum, 0, 96 * sizeof(float), 0);
    cudaMemsetAsync(sq,  0, 96 * sizeof(float), 0);
    gemm_kernel<16, 2, 32><<<(M + 255) / 256, 64>>>(h4, sc4, sh4, nullptr,
                                                    nullptr, nullptr, nullptr,
                                                    96, 96, w5, b5, h5, sum, sq, M);
    finalize_kernel<<<1, 16>>>(sum, sq, g5, be5, sc5, sh5, 16, M);
    norm_kernel<<<(M * 4 + 255) / 256, 256>>>(h5, sc5, sh5, out, M * 4, 4);

    (void)in_sizes; (void)n_in; (void)out_size;
}